// round 3
// baseline (speedup 1.0000x reference)
#include <cuda_runtime.h>
#include <math.h>

// ---------------- problem constants ----------------
#define H1 128
#define W1 160
#define H2 256
#define W2 320
#define HWS1 (H1*W1)   // 20480
#define HWS2 (H2*W2)   // 81920
#define ND1 48
#define ND2 8
#define C1 32
#define C2 16

// ---------------- scratch (device globals; no allocation allowed) ----------------
__device__ float g_rot[2][2][9];
__device__ float g_trans[2][2][3];
__device__ float g_dmin, g_dstep;

// 9 depth-folded conv planes: stage1 9*48*20480 = 8.8M floats (35.4 MB).
// stage2 needs 9*8*81920 = 5.9M floats -> fits in same buffer.
__device__ float g_B[9 * ND1 * HWS1];

// ---------------- setup: compose projections, invert ref, per-view rot/trans ----------------
__device__ void mat4_inv_d(const double* M, double* out) {
    double a[4][8];
    for (int i = 0; i < 4; i++)
        for (int j = 0; j < 4; j++) { a[i][j] = M[i*4+j]; a[i][j+4] = (i==j) ? 1.0 : 0.0; }
    for (int col = 0; col < 4; col++) {
        int piv = col; double best = fabs(a[col][col]);
        for (int r = col+1; r < 4; r++) if (fabs(a[r][col]) > best) { best = fabs(a[r][col]); piv = r; }
        if (piv != col) for (int j = 0; j < 8; j++) { double t = a[col][j]; a[col][j] = a[piv][j]; a[piv][j] = t; }
        double d = a[col][col];
        for (int j = 0; j < 8; j++) a[col][j] /= d;
        for (int r = 0; r < 4; r++) if (r != col) {
            double f = a[r][col];
            for (int j = 0; j < 8; j++) a[r][j] -= f * a[col][j];
        }
    }
    for (int i = 0; i < 4; i++) for (int j = 0; j < 4; j++) out[i*4+j] = a[i][j+4];
}

__global__ void setup_kernel(const float* __restrict__ proj1,
                             const float* __restrict__ proj2,
                             const float* __restrict__ depthv) {
    if (threadIdx.x != 0 || blockIdx.x != 0) return;
    for (int s = 0; s < 2; s++) {
        const float* P = s ? proj2 : proj1;   // (3 views, 2, 4, 4)
        double comp[3][16];
        for (int v = 0; v < 3; v++) {
            const float* E   = P + v*32;
            const float* Kin = P + v*32 + 16;
            for (int i = 0; i < 16; i++) comp[v][i] = (double)E[i];
            for (int i = 0; i < 3; i++)
                for (int j = 0; j < 4; j++) {
                    double t = 0.0;
                    for (int k = 0; k < 3; k++) t += (double)Kin[i*4+k] * (double)E[k*4+j];
                    comp[v][i*4+j] = t;
                }
        }
        double inv[16];
        mat4_inv_d(comp[0], inv);
        for (int v = 1; v < 3; v++) {
            double R[16];
            for (int i = 0; i < 4; i++)
                for (int j = 0; j < 4; j++) {
                    double t = 0.0;
                    for (int k = 0; k < 4; k++) t += comp[v][i*4+k] * inv[k*4+j];
                    R[i*4+j] = t;
                }
            for (int i = 0; i < 3; i++) {
                for (int j = 0; j < 3; j++) g_rot[s][v-1][i*3+j] = (float)R[i*4+j];
                g_trans[s][v-1][i] = (float)R[i*4+3];
            }
        }
    }
    g_dmin  = depthv[0];
    g_dstep = (depthv[ND1-1] - depthv[0]) / (float)(ND1 - 1);
}

// ---------------- 2x bilinear upsample sample (jax.image.resize 'bilinear') ----------------
__device__ __forceinline__ float resize2x_sample(const float* __restrict__ src, int h, int w) {
    float fy = 0.5f * (float)h - 0.25f;
    float fx = 0.5f * (float)w - 0.25f;
    float y0f = floorf(fy), x0f = floorf(fx);
    float ty = fy - y0f, tx = fx - x0f;
    int y0 = (int)y0f, x0 = (int)x0f;
    int y0c = min(max(y0, 0), H1-1), y1c = min(max(y0+1, 0), H1-1);
    int x0c = min(max(x0, 0), W1-1), x1c = min(max(x0+1, 0), W1-1);
    float v00 = src[y0c*W1 + x0c], v01 = src[y0c*W1 + x1c];
    float v10 = src[y1c*W1 + x0c], v11 = src[y1c*W1 + x1c];
    return (v00*(1.f-tx) + v01*tx)*(1.f-ty) + (v10*(1.f-tx) + v11*tx)*ty;
}

// ---------------- pass1: warp + variance + channel&depth-reduced conv ----------------
// Thread handles one (h,w) column over a depth chunk [d_lo, d_hi). It streams
// var rows dv = d_lo-1 .. d_hi (with zero pad at volume edges), folding the
// depth dimension of the 3x3x3 conv via 3 rolling sets of 9 accumulators.
// Output: g_B[j][d][h][w] = sum_{kd,c} var[c][d+kd-1][h][w] * w[c][kd][j],
// so the epilogue only needs a 9-tap 2D gather.
template<int C, int D, int H, int W, int DCHUNK, bool STAGE2>
__global__ void __launch_bounds__(256)
pass1_kernel(const float* __restrict__ feats,   // (3, C, H, W)
             const float* __restrict__ wconv,   // (C, 27)
             int stage,
             const float* __restrict__ d1,      // stage2 only
             const float* __restrict__ v1) {
    constexpr int HW  = H * W;
    constexpr int NCH = D / DCHUNK;

    // transposed weights: sw[(kd*9+j)*C + c] = wconv[c*27 + kd*9 + j]
    __shared__ float sw[27 * C];
    for (int i = threadIdx.x; i < 27*C; i += blockDim.x) {
        int k = i / C, c = i % C;
        sw[i] = wconv[c*27 + k];
    }
    __syncthreads();
    const float4* swv = reinterpret_cast<const float4*>(sw);

    int idx = blockIdx.x * blockDim.x + threadIdx.x;
    if (idx >= NCH * HW) return;
    int hw    = idx % HW;
    int chunk = idx / HW;
    int h = hw / W, w = hw % W;
    int d_lo = chunk * DCHUNK;
    int d_hi = d_lo + DCHUNK;

    float base, step;
    if (STAGE2) {
        float cd = resize2x_sample(d1, h, w);
        float cv = resize2x_sample(v1, h, w);
        float low  = -fminf(cd, cv);
        step = (cv - low) / (float)(D - 1);
        base = cd + low + 1e-12f;
    } else {
        base = g_dmin;
        step = g_dstep;
    }

    // rolling accumulators: M -> output row dv-1, 0 -> dv, P -> dv+1
    float accM[9], acc0[9], accP[9];
    #pragma unroll
    for (int j = 0; j < 9; j++) { accM[j] = 0.f; acc0[j] = 0.f; accP[j] = 0.f; }

    const float* f0 = feats + hw;                   // ref view, channel-strided
    const float* f1 = feats + (size_t)(1*C) * HW;
    const float* f2 = feats + (size_t)(2*C) * HW;

    for (int dv = d_lo - 1; dv <= d_hi; dv++) {
        if (dv >= 0 && dv < D) {
            float depth = fmaf(step, (float)dv, base);

            int   off[2][4];
            float wt[2][4];
            #pragma unroll
            for (int v = 0; v < 2; v++) {
                const float* R = g_rot[stage][v];
                const float* T = g_trans[stage][v];
                float fx = (float)w, fy = (float)h;
                float px = (R[0]*fx + R[1]*fy + R[2]) * depth + T[0];
                float py = (R[3]*fx + R[4]*fy + R[5]) * depth + T[1];
                float pz = (R[6]*fx + R[7]*fy + R[8]) * depth + T[2];
                float iz = __fdividef(1.0f, pz);
                float gx = px * iz / (0.5f*(float)(W-1)) - 1.0f;
                float gy = py * iz / (0.5f*(float)(H-1)) - 1.0f;
                float ix = ((gx + 1.0f)*(float)W - 1.0f) * 0.5f;
                float iy = ((gy + 1.0f)*(float)H - 1.0f) * 0.5f;
                ix = fminf(fmaxf(ix, -8.0f), (float)(W+8));
                iy = fminf(fmaxf(iy, -8.0f), (float)(H+8));
                float x0f = floorf(ix), y0f = floorf(iy);
                float tx = ix - x0f, ty = iy - y0f;
                int x0 = (int)x0f, y0 = (int)y0f;
                bool vx0 = (x0   >= 0) && (x0   <= W-1);
                bool vx1 = (x0+1 >= 0) && (x0+1 <= W-1);
                bool vy0 = (y0   >= 0) && (y0   <= H-1);
                bool vy1 = (y0+1 >= 0) && (y0+1 <= H-1);
                int x0c = min(max(x0,   0), W-1), x1c = min(max(x0+1, 0), W-1);
                int y0c = min(max(y0,   0), H-1), y1c = min(max(y0+1, 0), H-1);
                off[v][0] = y0c*W + x0c;  off[v][1] = y0c*W + x1c;
                off[v][2] = y1c*W + x0c;  off[v][3] = y1c*W + x1c;
                wt[v][0] = (vx0 && vy0) ? (1.f-tx)*(1.f-ty) : 0.f;
                wt[v][1] = (vx1 && vy0) ? tx*(1.f-ty)       : 0.f;
                wt[v][2] = (vx0 && vy1) ? (1.f-tx)*ty       : 0.f;
                wt[v][3] = (vx1 && vy1) ? tx*ty             : 0.f;
            }

            #pragma unroll
            for (int cg = 0; cg < C/4; cg++) {
                float v4[4];
                #pragma unroll
                for (int u = 0; u < 4; u++) {
                    int c = cg*4 + u;
                    const float* b1p = f1 + (size_t)c * HW;
                    const float* b2p = f2 + (size_t)c * HW;
                    float r  = f0[(size_t)c * HW];
                    float a1 = wt[0][0]*b1p[off[0][0]] + wt[0][1]*b1p[off[0][1]]
                             + wt[0][2]*b1p[off[0][2]] + wt[0][3]*b1p[off[0][3]];
                    float a2 = wt[1][0]*b2p[off[1][0]] + wt[1][1]*b2p[off[1][1]]
                             + wt[1][2]*b2p[off[1][2]] + wt[1][3]*b2p[off[1][3]];
                    float s = r + a1 + a2;
                    float q = r*r + a1*a1 + a2*a2;
                    float m = s * (1.0f/3.0f);
                    v4[u] = q * (1.0f/3.0f) - m*m;
                }
                #pragma unroll
                for (int j = 0; j < 9; j++) {
                    float4 w0 = swv[(0*9 + j)*(C/4) + cg];   // kd=0 -> out dv+1
                    float4 w1 = swv[(1*9 + j)*(C/4) + cg];   // kd=1 -> out dv
                    float4 w2 = swv[(2*9 + j)*(C/4) + cg];   // kd=2 -> out dv-1
                    accP[j] += v4[0]*w0.x + v4[1]*w0.y + v4[2]*w0.z + v4[3]*w0.w;
                    acc0[j] += v4[0]*w1.x + v4[1]*w1.y + v4[2]*w1.z + v4[3]*w1.w;
                    accM[j] += v4[0]*w2.x + v4[1]*w2.y + v4[2]*w2.z + v4[3]*w2.w;
                }
            }
        }

        // output row dv-1 is now complete
        int dout = dv - 1;
        if (dout >= d_lo && dout < d_hi) {
            #pragma unroll
            for (int j = 0; j < 9; j++)
                g_B[(size_t)j*(D*HW) + (size_t)dout*HW + hw] = accM[j];
        }
        #pragma unroll
        for (int j = 0; j < 9; j++) { accM[j] = acc0[j]; acc0[j] = accP[j]; accP[j] = 0.f; }
    }
}

// ---------------- fused epilogue: 9-tap 2D gather -> softmax -> depth/conf/var ----------------
template<int D, int H, int W, bool STAGE2>
__global__ void __launch_bounds__(256)
pixel_kernel(const float* __restrict__ bias,
             const float* __restrict__ d1, const float* __restrict__ v1,
             float* __restrict__ outd,
             float* __restrict__ outc,
             float* __restrict__ outv) {
    constexpr int HW = H * W;
    int p = blockIdx.x * blockDim.x + threadIdx.x;
    if (p >= HW) return;
    int h = p / W, w = p % W;

    int   joff[9];
    float jms[9];
    #pragma unroll
    for (int kh = 0; kh < 3; kh++)
        #pragma unroll
        for (int kw = 0; kw < 3; kw++) {
            int hh = h + kh - 1, ww = w + kw - 1;
            bool v = (hh >= 0) && (hh < H) && (ww >= 0) && (ww < W);
            joff[kh*3+kw] = v ? hh*W + ww : 0;
            jms[kh*3+kw]  = v ? 1.f : 0.f;
        }

    float bb = bias[0];
    float e[D];
    float mx = -1e30f;
    #pragma unroll
    for (int d = 0; d < D; d++) {
        float s = bb;
        #pragma unroll
        for (int j = 0; j < 9; j++)
            s += jms[j] * g_B[(size_t)j*(D*HW) + (size_t)d*HW + joff[j]];
        e[d] = s;
        mx = fmaxf(mx, s);
    }
    float sum = 0.f;
    #pragma unroll
    for (int d = 0; d < D; d++) { e[d] = expf(e[d] - mx); sum += e[d]; }
    float inv = 1.0f / sum;
    float m1 = 0.f;
    #pragma unroll
    for (int d = 0; d < D; d++) {
        float pr = e[d] * inv;
        e[d] = pr;
        m1 += pr * (float)d;
    }

    float base, step;
    if (STAGE2) {
        float cd = resize2x_sample(d1, h, w);
        float cv = resize2x_sample(v1, h, w);
        float low  = -fminf(cd, cv);
        step = (cv - low) / (float)(D - 1);
        base = cd + low + 1e-12f;
    } else {
        base = g_dmin;
        step = g_dstep;
    }

    float depth = fmaf(step, m1, base);
    float var = 0.f;
    #pragma unroll
    for (int d = 0; d < D; d++) {
        float t = step * ((float)d - m1);
        var += e[d] * t * t;
    }
    int di = min(max((int)m1, 0), D-1);
    float conf = 0.f;
    #pragma unroll
    for (int d = 0; d < D; d++)
        if (d >= di-1 && d <= di+2) conf += e[d];

    outd[p] = depth;
    outc[p] = conf;
    outv[p] = 1.5f * sqrtf(fmaxf(var, 0.f));
}

// ---------------- launch ----------------
extern "C" void kernel_launch(void* const* d_in, const int* in_sizes, int n_in,
                              void* d_out, int out_size) {
    const float* feats1 = (const float*)d_in[0];
    const float* feats2 = (const float*)d_in[1];
    const float* proj1  = (const float*)d_in[2];
    const float* proj2  = (const float*)d_in[3];
    const float* depthv = (const float*)d_in[4];
    const float* w1     = (const float*)d_in[6];
    const float* b1     = (const float*)d_in[7];
    const float* w2     = (const float*)d_in[8];
    const float* b2     = (const float*)d_in[9];

    float* out = (float*)d_out;
    float* o_d1 = out;
    float* o_c1 = out + HWS1;
    float* o_v1 = out + 2*HWS1;
    float* o_d2 = out + 3*HWS1;
    float* o_c2 = out + 3*HWS1 + HWS2;
    float* o_v2 = out + 3*HWS1 + 2*HWS2;

    setup_kernel<<<1, 1>>>(proj1, proj2, depthv);

    // ---- stage 1 (C=32, D=48, 128x160) ----
    {
        constexpr int DCHUNK = 8;
        int nthr = (ND1/DCHUNK) * HWS1;                    // 122880
        pass1_kernel<C1, ND1, H1, W1, DCHUNK, false>
            <<<(nthr + 255)/256, 256>>>(feats1, w1, 0, nullptr, nullptr);
        pixel_kernel<ND1, H1, W1, false>
            <<<(HWS1 + 255)/256, 256>>>(b1, nullptr, nullptr, o_d1, o_c1, o_v1);
    }

    // ---- stage 2 (C=16, D=8, 256x320) ----
    {
        constexpr int DCHUNK = 8;                          // full column
        int nthr = (ND2/DCHUNK) * HWS2;                    // 81920
        pass1_kernel<C2, ND2, H2, W2, DCHUNK, true>
            <<<(nthr + 255)/256, 256>>>(feats2, w2, 1, o_d1, o_v1);
        pixel_kernel<ND2, H2, W2, true>
            <<<(HWS2 + 255)/256, 256>>>(b2, o_d1, o_v1, o_d2, o_c2, o_v2);
    }
}

// round 4
// speedup vs baseline: 1.6824x; 1.6824x over previous
#include <cuda_runtime.h>
#include <math.h>

// ---------------- problem constants ----------------
#define H1 128
#define W1 160
#define H2 256
#define W2 320
#define HWS1 (H1*W1)   // 20480
#define HWS2 (H2*W2)   // 81920
#define ND1 48
#define ND2 8
#define C1 32
#define C2 16

// ---------------- scratch (device globals; no allocation allowed) ----------------
__device__ float g_rot[2][2][9];
__device__ float g_trans[2][2][3];
__device__ float g_dmin, g_dstep;

// 27 channel-reduced conv planes. stage1: 27*48*20480 = 26.5M floats (106MB).
// stage2: 27*8*81920 = 17.7M floats -> fits in same buffer.
__device__ float g_G[27 * ND1 * HWS1];
// stage-2 per-pixel depth base/step
__device__ float g_bs[2 * HWS2];

// ---------------- f32x2 packed math (sm_103a FFMA2 via PTX) ----------------
__device__ __forceinline__ unsigned long long pk2(float a, float b) {
    unsigned long long r;
    asm("mov.b64 %0, {%1, %2};" : "=l"(r) : "f"(a), "f"(b));
    return r;
}
__device__ __forceinline__ void fma2(unsigned long long& d,
                                     unsigned long long a, unsigned long long b) {
    asm("fma.rn.f32x2 %0, %1, %2, %0;" : "+l"(d) : "l"(a), "l"(b));
}
__device__ __forceinline__ float2 upk2(unsigned long long v) {
    float2 r;
    asm("mov.b64 {%0, %1}, %2;" : "=f"(r.x), "=f"(r.y) : "l"(v));
    return r;
}

// ---------------- setup: compose projections, invert ref, per-view rot/trans ----------------
__device__ void mat4_inv_d(const double* M, double* out) {
    double a[4][8];
    for (int i = 0; i < 4; i++)
        for (int j = 0; j < 4; j++) { a[i][j] = M[i*4+j]; a[i][j+4] = (i==j) ? 1.0 : 0.0; }
    for (int col = 0; col < 4; col++) {
        int piv = col; double best = fabs(a[col][col]);
        for (int r = col+1; r < 4; r++) if (fabs(a[r][col]) > best) { best = fabs(a[r][col]); piv = r; }
        if (piv != col) for (int j = 0; j < 8; j++) { double t = a[col][j]; a[col][j] = a[piv][j]; a[piv][j] = t; }
        double d = a[col][col];
        for (int j = 0; j < 8; j++) a[col][j] /= d;
        for (int r = 0; r < 4; r++) if (r != col) {
            double f = a[r][col];
            for (int j = 0; j < 8; j++) a[r][j] -= f * a[col][j];
        }
    }
    for (int i = 0; i < 4; i++) for (int j = 0; j < 4; j++) out[i*4+j] = a[i][j+4];
}

__global__ void setup_kernel(const float* __restrict__ proj1,
                             const float* __restrict__ proj2,
                             const float* __restrict__ depthv) {
    if (threadIdx.x != 0 || blockIdx.x != 0) return;
    for (int s = 0; s < 2; s++) {
        const float* P = s ? proj2 : proj1;   // (3 views, 2, 4, 4)
        double comp[3][16];
        for (int v = 0; v < 3; v++) {
            const float* E   = P + v*32;
            const float* Kin = P + v*32 + 16;
            for (int i = 0; i < 16; i++) comp[v][i] = (double)E[i];
            for (int i = 0; i < 3; i++)
                for (int j = 0; j < 4; j++) {
                    double t = 0.0;
                    for (int k = 0; k < 3; k++) t += (double)Kin[i*4+k] * (double)E[k*4+j];
                    comp[v][i*4+j] = t;
                }
        }
        double inv[16];
        mat4_inv_d(comp[0], inv);
        for (int v = 1; v < 3; v++) {
            double R[16];
            for (int i = 0; i < 4; i++)
                for (int j = 0; j < 4; j++) {
                    double t = 0.0;
                    for (int k = 0; k < 4; k++) t += comp[v][i*4+k] * inv[k*4+j];
                    R[i*4+j] = t;
                }
            for (int i = 0; i < 3; i++) {
                for (int j = 0; j < 3; j++) g_rot[s][v-1][i*3+j] = (float)R[i*4+j];
                g_trans[s][v-1][i] = (float)R[i*4+3];
            }
        }
    }
    g_dmin  = depthv[0];
    g_dstep = (depthv[ND1-1] - depthv[0]) / (float)(ND1 - 1);
}

// ---------------- 2x bilinear upsample sample (jax.image.resize 'bilinear') ----------------
__device__ __forceinline__ float resize2x_sample(const float* __restrict__ src, int h, int w) {
    float fy = 0.5f * (float)h - 0.25f;
    float fx = 0.5f * (float)w - 0.25f;
    float y0f = floorf(fy), x0f = floorf(fx);
    float ty = fy - y0f, tx = fx - x0f;
    int y0 = (int)y0f, x0 = (int)x0f;
    int y0c = min(max(y0, 0), H1-1), y1c = min(max(y0+1, 0), H1-1);
    int x0c = min(max(x0, 0), W1-1), x1c = min(max(x0+1, 0), W1-1);
    float v00 = src[y0c*W1 + x0c], v01 = src[y0c*W1 + x1c];
    float v10 = src[y1c*W1 + x0c], v11 = src[y1c*W1 + x1c];
    return (v00*(1.f-tx) + v01*tx)*(1.f-ty) + (v10*(1.f-tx) + v11*tx)*ty;
}

// stage-2 depth hypothesis base/step per pixel
__global__ void bs2_kernel(const float* __restrict__ d1, const float* __restrict__ v1) {
    int p = blockIdx.x * blockDim.x + threadIdx.x;
    if (p >= HWS2) return;
    int h = p / W2, w = p % W2;
    float cd = resize2x_sample(d1, h, w);
    float cv = resize2x_sample(v1, h, w);
    float low  = -fminf(cd, cv);
    g_bs[p]        = cd + low + 1e-12f;
    g_bs[HWS2 + p] = (cv - low) / (float)(ND2 - 1);
}

// ---------------- pass1: warp + variance + channel-reduced conv taps ----------------
// One thread per voxel. acc[k] = sum_c var[c] * w[c][k] for the 27 taps, using
// packed f32x2 FMAs (2 channels per op) and 128-bit broadcast SMEM weight loads.
template<int C, int D, int H, int W, bool STAGE2>
__global__ void __launch_bounds__(256)
pass1_kernel(const float* __restrict__ feats,   // (3, C, H, W)
             const float* __restrict__ wconv,   // (C, 27)
             int stage) {
    constexpr int HW = H * W;
    constexpr int NP = C / 2;   // channel pairs

    // packed transposed weights: swp[k*NP + p] = (w[2p][k], w[2p+1][k])
    __shared__ unsigned long long swp[27 * NP];
    for (int i = threadIdx.x; i < 27*NP; i += blockDim.x) {
        int k = i / NP, p = i % NP;
        unsigned int lo = __float_as_uint(wconv[(2*p    )*27 + k]);
        unsigned int hi = __float_as_uint(wconv[(2*p + 1)*27 + k]);
        swp[i] = (unsigned long long)lo | ((unsigned long long)hi << 32);
    }
    __syncthreads();
    const ulonglong2* swv = reinterpret_cast<const ulonglong2*>(swp);

    int idx = blockIdx.x * blockDim.x + threadIdx.x;
    if (idx >= D * HW) return;
    int hw = idx % HW;
    int d  = idx / HW;
    int h = hw / W, w = hw % W;

    float base, step;
    if (STAGE2) { base = g_bs[hw]; step = g_bs[HWS2 + hw]; }
    else        { base = g_dmin;   step = g_dstep; }
    float depth = fmaf(step, (float)d, base);

    int   off[2][4];
    float wt[2][4];
    #pragma unroll
    for (int v = 0; v < 2; v++) {
        const float* R = g_rot[stage][v];
        const float* T = g_trans[stage][v];
        float fx = (float)w, fy = (float)h;
        float px = (R[0]*fx + R[1]*fy + R[2]) * depth + T[0];
        float py = (R[3]*fx + R[4]*fy + R[5]) * depth + T[1];
        float pz = (R[6]*fx + R[7]*fy + R[8]) * depth + T[2];
        float iz = __fdividef(1.0f, pz);
        float gx = px * iz / (0.5f*(float)(W-1)) - 1.0f;
        float gy = py * iz / (0.5f*(float)(H-1)) - 1.0f;
        float ix = ((gx + 1.0f)*(float)W - 1.0f) * 0.5f;
        float iy = ((gy + 1.0f)*(float)H - 1.0f) * 0.5f;
        ix = fminf(fmaxf(ix, -8.0f), (float)(W+8));
        iy = fminf(fmaxf(iy, -8.0f), (float)(H+8));
        float x0f = floorf(ix), y0f = floorf(iy);
        float tx = ix - x0f, ty = iy - y0f;
        int x0 = (int)x0f, y0 = (int)y0f;
        bool vx0 = (x0   >= 0) && (x0   <= W-1);
        bool vx1 = (x0+1 >= 0) && (x0+1 <= W-1);
        bool vy0 = (y0   >= 0) && (y0   <= H-1);
        bool vy1 = (y0+1 >= 0) && (y0+1 <= H-1);
        int x0c = min(max(x0,   0), W-1), x1c = min(max(x0+1, 0), W-1);
        int y0c = min(max(y0,   0), H-1), y1c = min(max(y0+1, 0), H-1);
        off[v][0] = y0c*W + x0c;  off[v][1] = y0c*W + x1c;
        off[v][2] = y1c*W + x0c;  off[v][3] = y1c*W + x1c;
        wt[v][0] = (vx0 && vy0) ? (1.f-tx)*(1.f-ty) : 0.f;
        wt[v][1] = (vx1 && vy0) ? tx*(1.f-ty)       : 0.f;
        wt[v][2] = (vx0 && vy1) ? (1.f-tx)*ty       : 0.f;
        wt[v][3] = (vx1 && vy1) ? tx*ty             : 0.f;
    }

    const float* f0 = feats + hw;                   // ref view, channel-strided
    const float* f1 = feats + (size_t)(1*C) * HW;
    const float* f2 = feats + (size_t)(2*C) * HW;

    unsigned long long acc[27];
    #pragma unroll
    for (int k = 0; k < 27; k++) acc[k] = 0ULL;

    #pragma unroll
    for (int cg = 0; cg < C/4; cg++) {
        float v4[4];
        #pragma unroll
        for (int u = 0; u < 4; u++) {
            int c = cg*4 + u;
            const float* b1p = f1 + (size_t)c * HW;
            const float* b2p = f2 + (size_t)c * HW;
            float r  = f0[(size_t)c * HW];
            float a1 = wt[0][0]*b1p[off[0][0]] + wt[0][1]*b1p[off[0][1]]
                     + wt[0][2]*b1p[off[0][2]] + wt[0][3]*b1p[off[0][3]];
            float a2 = wt[1][0]*b2p[off[1][0]] + wt[1][1]*b2p[off[1][1]]
                     + wt[1][2]*b2p[off[1][2]] + wt[1][3]*b2p[off[1][3]];
            float s = r + a1 + a2;
            float q = r*r + a1*a1 + a2*a2;
            float m = s * (1.0f/3.0f);
            v4[u] = q * (1.0f/3.0f) - m*m;
        }
        unsigned long long va = pk2(v4[0], v4[1]);
        unsigned long long vb = pk2(v4[2], v4[3]);
        #pragma unroll
        for (int k = 0; k < 27; k++) {
            ulonglong2 wv = swv[k*(C/4) + cg];   // (pair c0c1, pair c2c3)
            fma2(acc[k], va, wv.x);
            fma2(acc[k], vb, wv.y);
        }
    }

    #pragma unroll
    for (int k = 0; k < 27; k++) {
        float2 t = upk2(acc[k]);
        g_G[(size_t)k*(D*HW) + idx] = t.x + t.y;
    }
}

// ---------------- fused epilogue: 27-tap gather -> softmax -> depth/conf/var ----------------
template<int D, int H, int W, bool STAGE2>
__global__ void __launch_bounds__(256)
pixel_kernel(const float* __restrict__ bias,
             float* __restrict__ outd,
             float* __restrict__ outc,
             float* __restrict__ outv) {
    constexpr int HW = H * W;
    int p = blockIdx.x * blockDim.x + threadIdx.x;
    if (p >= HW) return;
    int h = p / W, w = p % W;

    int   joff[9];
    float jms[9];
    #pragma unroll
    for (int kh = 0; kh < 3; kh++)
        #pragma unroll
        for (int kw = 0; kw < 3; kw++) {
            int hh = h + kh - 1, ww = w + kw - 1;
            bool v = (hh >= 0) && (hh < H) && (ww >= 0) && (ww < W);
            joff[kh*3+kw] = v ? hh*W + ww : 0;
            jms[kh*3+kw]  = v ? 1.f : 0.f;
        }

    float bb = bias[0];
    float e[D];
    float mx = -1e30f;
    #pragma unroll
    for (int d = 0; d < D; d++) {
        float s = bb;
        #pragma unroll
        for (int kd = 0; kd < 3; kd++) {
            int dd = d + kd - 1;
            if (dd < 0 || dd >= D) continue;
            #pragma unroll
            for (int j = 0; j < 9; j++)
                s += jms[j] * g_G[(size_t)(kd*9 + j)*(D*HW) + (size_t)dd*HW + joff[j]];
        }
        e[d] = s;
        mx = fmaxf(mx, s);
    }
    float sum = 0.f;
    #pragma unroll
    for (int d = 0; d < D; d++) { e[d] = expf(e[d] - mx); sum += e[d]; }
    float inv = 1.0f / sum;
    float m1 = 0.f;
    #pragma unroll
    for (int d = 0; d < D; d++) {
        float pr = e[d] * inv;
        e[d] = pr;
        m1 += pr * (float)d;
    }

    float base, step;
    if (STAGE2) { base = g_bs[p]; step = g_bs[HWS2 + p]; }
    else        { base = g_dmin; step = g_dstep; }

    float depth = fmaf(step, m1, base);
    float var = 0.f;
    #pragma unroll
    for (int d = 0; d < D; d++) {
        float t = step * ((float)d - m1);
        var += e[d] * t * t;
    }
    int di = min(max((int)m1, 0), D-1);
    float conf = 0.f;
    #pragma unroll
    for (int d = 0; d < D; d++)
        if (d >= di-1 && d <= di+2) conf += e[d];

    outd[p] = depth;
    outc[p] = conf;
    outv[p] = 1.5f * sqrtf(fmaxf(var, 0.f));
}

// ---------------- launch ----------------
extern "C" void kernel_launch(void* const* d_in, const int* in_sizes, int n_in,
                              void* d_out, int out_size) {
    const float* feats1 = (const float*)d_in[0];
    const float* feats2 = (const float*)d_in[1];
    const float* proj1  = (const float*)d_in[2];
    const float* proj2  = (const float*)d_in[3];
    const float* depthv = (const float*)d_in[4];
    const float* w1     = (const float*)d_in[6];
    const float* b1     = (const float*)d_in[7];
    const float* w2     = (const float*)d_in[8];
    const float* b2     = (const float*)d_in[9];

    float* out = (float*)d_out;
    float* o_d1 = out;
    float* o_c1 = out + HWS1;
    float* o_v1 = out + 2*HWS1;
    float* o_d2 = out + 3*HWS1;
    float* o_c2 = out + 3*HWS1 + HWS2;
    float* o_v2 = out + 3*HWS1 + 2*HWS2;

    setup_kernel<<<1, 1>>>(proj1, proj2, depthv);

    // ---- stage 1 (C=32, D=48, 128x160) ----
    {
        int nvox = ND1 * HWS1;   // 983040
        pass1_kernel<C1, ND1, H1, W1, false>
            <<<(nvox + 255)/256, 256>>>(feats1, w1, 0);
        pixel_kernel<ND1, H1, W1, false>
            <<<(HWS1 + 255)/256, 256>>>(b1, o_d1, o_c1, o_v1);
    }

    // ---- stage 2 (C=16, D=8, 256x320) ----
    {
        int nvox = ND2 * HWS2;   // 655360
        bs2_kernel<<<(HWS2 + 255)/256, 256>>>(o_d1, o_v1);
        pass1_kernel<C2, ND2, H2, W2, true>
            <<<(nvox + 255)/256, 256>>>(feats2, w2, 1);
        pixel_kernel<ND2, H2, W2, true>
            <<<(HWS2 + 255)/256, 256>>>(b2, o_d2, o_c2, o_v2);
    }
}

// round 5
// speedup vs baseline: 1.8735x; 1.1136x over previous
#include <cuda_runtime.h>
#include <math.h>

// ---------------- problem constants ----------------
#define H1 128
#define W1 160
#define H2 256
#define W2 320
#define HWS1 (H1*W1)   // 20480
#define HWS2 (H2*W2)   // 81920
#define ND1 48
#define ND2 8
#define C1 32
#define C2 16

// ---------------- scratch (device globals; no allocation allowed) ----------------
__device__ float g_rot[2][2][9];
__device__ float g_trans[2][2][3];
__device__ float g_dmin, g_dstep;
__device__ float g_pad[32];

// 27 channel-reduced conv planes. stage1: 27*48*20480 floats (106MB).
// stage2: 27*8*81920 -> fits in same buffer.
__device__ float g_G[27 * ND1 * HWS1];
__device__ float g_cost[ND1 * HWS1];      // stage2: 8*81920 fits
__device__ float g_bs[2 * HWS2];          // stage-2 per-pixel depth base/step

// ---------------- setup ----------------
__device__ void mat4_inv_d(const double* M, double* out) {
    double a[4][8];
    for (int i = 0; i < 4; i++)
        for (int j = 0; j < 4; j++) { a[i][j] = M[i*4+j]; a[i][j+4] = (i==j) ? 1.0 : 0.0; }
    for (int col = 0; col < 4; col++) {
        int piv = col; double best = fabs(a[col][col]);
        for (int r = col+1; r < 4; r++) if (fabs(a[r][col]) > best) { best = fabs(a[r][col]); piv = r; }
        if (piv != col) for (int j = 0; j < 8; j++) { double t = a[col][j]; a[col][j] = a[piv][j]; a[piv][j] = t; }
        double d = a[col][col];
        for (int j = 0; j < 8; j++) a[col][j] /= d;
        for (int r = 0; r < 4; r++) if (r != col) {
            double f = a[r][col];
            for (int j = 0; j < 8; j++) a[r][j] -= f * a[col][j];
        }
    }
    for (int i = 0; i < 4; i++) for (int j = 0; j < 4; j++) out[i*4+j] = a[i][j+4];
}

__global__ void setup_kernel(const float* __restrict__ proj1,
                             const float* __restrict__ proj2,
                             const float* __restrict__ depthv) {
    if (threadIdx.x != 0 || blockIdx.x != 0) return;
    for (int s = 0; s < 2; s++) {
        const float* P = s ? proj2 : proj1;   // (3 views, 2, 4, 4)
        double comp[3][16];
        for (int v = 0; v < 3; v++) {
            const float* E   = P + v*32;
            const float* Kin = P + v*32 + 16;
            for (int i = 0; i < 16; i++) comp[v][i] = (double)E[i];
            for (int i = 0; i < 3; i++)
                for (int j = 0; j < 4; j++) {
                    double t = 0.0;
                    for (int k = 0; k < 3; k++) t += (double)Kin[i*4+k] * (double)E[k*4+j];
                    comp[v][i*4+j] = t;
                }
        }
        double inv[16];
        mat4_inv_d(comp[0], inv);
        for (int v = 1; v < 3; v++) {
            double R[16];
            for (int i = 0; i < 4; i++)
                for (int j = 0; j < 4; j++) {
                    double t = 0.0;
                    for (int k = 0; k < 4; k++) t += comp[v][i*4+k] * inv[k*4+j];
                    R[i*4+j] = t;
                }
            for (int i = 0; i < 3; i++) {
                for (int j = 0; j < 3; j++) g_rot[s][v-1][i*3+j] = (float)R[i*4+j];
                g_trans[s][v-1][i] = (float)R[i*4+3];
            }
        }
    }
    g_dmin  = depthv[0];
    g_dstep = (depthv[ND1-1] - depthv[0]) / (float)(ND1 - 1);
}

// no-op pad kernels so the profiler's 4th-launch capture lands on pass1_s1
__global__ void pad_kernel(int v) {
    if (blockIdx.x == 0 && threadIdx.x == 0) g_pad[v] = (float)v;
}

// ---------------- 2x bilinear upsample sample ----------------
__device__ __forceinline__ float resize2x_sample(const float* __restrict__ src, int h, int w) {
    float fy = 0.5f * (float)h - 0.25f;
    float fx = 0.5f * (float)w - 0.25f;
    float y0f = floorf(fy), x0f = floorf(fx);
    float ty = fy - y0f, tx = fx - x0f;
    int y0 = (int)y0f, x0 = (int)x0f;
    int y0c = min(max(y0, 0), H1-1), y1c = min(max(y0+1, 0), H1-1);
    int x0c = min(max(x0, 0), W1-1), x1c = min(max(x0+1, 0), W1-1);
    float v00 = src[y0c*W1 + x0c], v01 = src[y0c*W1 + x1c];
    float v10 = src[y1c*W1 + x0c], v11 = src[y1c*W1 + x1c];
    return (v00*(1.f-tx) + v01*tx)*(1.f-ty) + (v10*(1.f-tx) + v11*tx)*ty;
}

__global__ void bs2_kernel(const float* __restrict__ d1, const float* __restrict__ v1) {
    int p = blockIdx.x * blockDim.x + threadIdx.x;
    if (p >= HWS2) return;
    int h = p / W2, w = p % W2;
    float cd = resize2x_sample(d1, h, w);
    float cv = resize2x_sample(v1, h, w);
    float low  = -fminf(cd, cv);
    g_bs[p]        = cd + low + 1e-12f;
    g_bs[HWS2 + p] = (cv - low) / (float)(ND2 - 1);
}

// ---------------- pass1: warp + variance + channel-reduced conv taps ----------------
template<int C, int D, int H, int W, bool STAGE2>
__global__ void __launch_bounds__(128)
pass1_kernel(const float* __restrict__ feats,   // (3, C, H, W)
             const float* __restrict__ wconv,   // (C, 27)
             int stage) {
    constexpr int HW = H * W;

    // transposed weights: sw[k*C + c] = wconv[c*27 + k], read as float4 over c
    __shared__ float sw[27 * C];
    for (int i = threadIdx.x; i < 27*C; i += blockDim.x) {
        int k = i / C, c = i % C;
        sw[i] = wconv[c*27 + k];
    }
    __syncthreads();
    const float4* swv = reinterpret_cast<const float4*>(sw);

    int idx = blockIdx.x * blockDim.x + threadIdx.x;
    if (idx >= D * HW) return;
    int hw = idx % HW;
    int d  = idx / HW;
    int h = hw / W, w = hw % W;

    float base, step;
    if (STAGE2) { base = g_bs[hw]; step = g_bs[HWS2 + hw]; }
    else        { base = g_dmin;   step = g_dstep; }
    float depth = fmaf(step, (float)d, base);

    int   off[2][4];
    float wt[2][4];
    #pragma unroll
    for (int v = 0; v < 2; v++) {
        const float* R = g_rot[stage][v];
        const float* T = g_trans[stage][v];
        float fx = (float)w, fy = (float)h;
        float px = (R[0]*fx + R[1]*fy + R[2]) * depth + T[0];
        float py = (R[3]*fx + R[4]*fy + R[5]) * depth + T[1];
        float pz = (R[6]*fx + R[7]*fy + R[8]) * depth + T[2];
        float iz = __fdividef(1.0f, pz);
        float gx = px * iz / (0.5f*(float)(W-1)) - 1.0f;
        float gy = py * iz / (0.5f*(float)(H-1)) - 1.0f;
        float ix = ((gx + 1.0f)*(float)W - 1.0f) * 0.5f;
        float iy = ((gy + 1.0f)*(float)H - 1.0f) * 0.5f;
        ix = fminf(fmaxf(ix, -8.0f), (float)(W+8));
        iy = fminf(fmaxf(iy, -8.0f), (float)(H+8));
        float x0f = floorf(ix), y0f = floorf(iy);
        float tx = ix - x0f, ty = iy - y0f;
        int x0 = (int)x0f, y0 = (int)y0f;
        bool vx0 = (x0   >= 0) && (x0   <= W-1);
        bool vx1 = (x0+1 >= 0) && (x0+1 <= W-1);
        bool vy0 = (y0   >= 0) && (y0   <= H-1);
        bool vy1 = (y0+1 >= 0) && (y0+1 <= H-1);
        int x0c = min(max(x0,   0), W-1), x1c = min(max(x0+1, 0), W-1);
        int y0c = min(max(y0,   0), H-1), y1c = min(max(y0+1, 0), H-1);
        off[v][0] = y0c*W + x0c;  off[v][1] = y0c*W + x1c;
        off[v][2] = y1c*W + x0c;  off[v][3] = y1c*W + x1c;
        wt[v][0] = (vx0 && vy0) ? (1.f-tx)*(1.f-ty) : 0.f;
        wt[v][1] = (vx1 && vy0) ? tx*(1.f-ty)       : 0.f;
        wt[v][2] = (vx0 && vy1) ? (1.f-tx)*ty       : 0.f;
        wt[v][3] = (vx1 && vy1) ? tx*ty             : 0.f;
    }

    const float* f0 = feats + hw;
    const float* f1 = feats + (size_t)(1*C) * HW;
    const float* f2 = feats + (size_t)(2*C) * HW;

    float acc[27];
    #pragma unroll
    for (int k = 0; k < 27; k++) acc[k] = 0.f;

    #pragma unroll
    for (int cg = 0; cg < C/4; cg++) {
        float v4[4];
        #pragma unroll
        for (int u = 0; u < 4; u++) {
            int c = cg*4 + u;
            const float* b1p = f1 + (size_t)c * HW;
            const float* b2p = f2 + (size_t)c * HW;
            float r  = f0[(size_t)c * HW];
            float a1 = wt[0][0]*b1p[off[0][0]] + wt[0][1]*b1p[off[0][1]]
                     + wt[0][2]*b1p[off[0][2]] + wt[0][3]*b1p[off[0][3]];
            float a2 = wt[1][0]*b2p[off[1][0]] + wt[1][1]*b2p[off[1][1]]
                     + wt[1][2]*b2p[off[1][2]] + wt[1][3]*b2p[off[1][3]];
            float s = r + a1 + a2;
            float q = r*r + a1*a1 + a2*a2;
            float m = s * (1.0f/3.0f);
            v4[u] = q * (1.0f/3.0f) - m*m;
        }
        #pragma unroll
        for (int k = 0; k < 27; k++) {
            float4 wv = swv[k*(C/4) + cg];
            acc[k] = fmaf(v4[0], wv.x, acc[k]);
            acc[k] = fmaf(v4[1], wv.y, acc[k]);
            acc[k] = fmaf(v4[2], wv.z, acc[k]);
            acc[k] = fmaf(v4[3], wv.w, acc[k]);
        }
    }

    #pragma unroll
    for (int k = 0; k < 27; k++)
        g_G[(size_t)k*(D*HW) + idx] = acc[k];
}

// ---------------- cost: 27-tap shifted-plane sum (zero-pad SAME) ----------------
template<int D, int H, int W>
__global__ void __launch_bounds__(256)
cost_kernel(const float* __restrict__ bias) {
    constexpr int HW = H * W;
    int idx = blockIdx.x * blockDim.x + threadIdx.x;
    if (idx >= D * HW) return;
    int hw = idx % HW;
    int d  = idx / HW;
    int h = hw / W, w = hw % W;
    float s = bias[0];
    #pragma unroll
    for (int kd = 0; kd < 3; kd++) {
        int dd = d + kd - 1;
        if (dd < 0 || dd >= D) continue;
        #pragma unroll
        for (int kh = 0; kh < 3; kh++) {
            int hh = h + kh - 1;
            if (hh < 0 || hh >= H) continue;
            #pragma unroll
            for (int kw = 0; kw < 3; kw++) {
                int ww = w + kw - 1;
                if (ww < 0 || ww >= W) continue;
                s += g_G[(size_t)(kd*9 + kh*3 + kw)*(D*HW) + (size_t)dd*HW + hh*W + ww];
            }
        }
    }
    g_cost[idx] = s;
}

// ---------------- per-pixel epilogue ----------------
template<int D, int H, int W, bool STAGE2>
__global__ void __launch_bounds__(256)
pixel_kernel(float* __restrict__ outd,
             float* __restrict__ outc,
             float* __restrict__ outv) {
    constexpr int HW = H * W;
    int p = blockIdx.x * blockDim.x + threadIdx.x;
    if (p >= HW) return;

    float e[D];
    float mx = -1e30f;
    #pragma unroll
    for (int d = 0; d < D; d++) { e[d] = g_cost[(size_t)d*HW + p]; mx = fmaxf(mx, e[d]); }
    float sum = 0.f;
    #pragma unroll
    for (int d = 0; d < D; d++) { e[d] = expf(e[d] - mx); sum += e[d]; }
    float inv = 1.0f / sum;
    float m1 = 0.f;
    #pragma unroll
    for (int d = 0; d < D; d++) {
        float pr = e[d] * inv;
        e[d] = pr;
        m1 += pr * (float)d;
    }

    float base, step;
    if (STAGE2) { base = g_bs[p]; step = g_bs[HWS2 + p]; }
    else        { base = g_dmin; step = g_dstep; }

    float depth = fmaf(step, m1, base);
    float var = 0.f;
    #pragma unroll
    for (int d = 0; d < D; d++) {
        float t = step * ((float)d - m1);
        var += e[d] * t * t;
    }
    int di = min(max((int)m1, 0), D-1);
    float conf = 0.f;
    #pragma unroll
    for (int d = 0; d < D; d++)
        if (d >= di-1 && d <= di+2) conf += e[d];

    outd[p] = depth;
    outc[p] = conf;
    outv[p] = 1.5f * sqrtf(fmaxf(var, 0.f));
}

// ---------------- launch ----------------
extern "C" void kernel_launch(void* const* d_in, const int* in_sizes, int n_in,
                              void* d_out, int out_size) {
    const float* feats1 = (const float*)d_in[0];
    const float* feats2 = (const float*)d_in[1];
    const float* proj1  = (const float*)d_in[2];
    const float* proj2  = (const float*)d_in[3];
    const float* depthv = (const float*)d_in[4];
    const float* w1     = (const float*)d_in[6];
    const float* b1     = (const float*)d_in[7];
    const float* w2     = (const float*)d_in[8];
    const float* b2     = (const float*)d_in[9];

    float* out = (float*)d_out;
    float* o_d1 = out;
    float* o_c1 = out + HWS1;
    float* o_v1 = out + 2*HWS1;
    float* o_d2 = out + 3*HWS1;
    float* o_c2 = out + 3*HWS1 + HWS2;
    float* o_v2 = out + 3*HWS1 + 2*HWS2;

    setup_kernel<<<1, 1>>>(proj1, proj2, depthv);   // launch 1
    pad_kernel<<<1, 32>>>(0);                       // launch 2
    pad_kernel<<<1, 32>>>(1);                       // launch 3

    // ---- stage 1 (C=32, D=48, 128x160) ----
    {
        int nvox = ND1 * HWS1;   // 983040
        pass1_kernel<C1, ND1, H1, W1, false>        // launch 4 (profiled)
            <<<(nvox + 127)/128, 128>>>(feats1, w1, 0);
        cost_kernel<ND1, H1, W1>
            <<<(nvox + 255)/256, 256>>>(b1);
        pixel_kernel<ND1, H1, W1, false>
            <<<(HWS1 + 255)/256, 256>>>(o_d1, o_c1, o_v1);
    }

    // ---- stage 2 (C=16, D=8, 256x320) ----
    {
        int nvox = ND2 * HWS2;   // 655360
        bs2_kernel<<<(HWS2 + 255)/256, 256>>>(o_d1, o_v1);
        pass1_kernel<C2, ND2, H2, W2, true>
            <<<(nvox + 127)/128, 128>>>(feats2, w2, 1);
        cost_kernel<ND2, H2, W2>
            <<<(nvox + 255)/256, 256>>>(b2);
        pixel_kernel<ND2, H2, W2, true>
            <<<(HWS2 + 255)/256, 256>>>(o_d2, o_c2, o_v2);
    }
}

// round 6
// speedup vs baseline: 1.9965x; 1.0657x over previous
#include <cuda_runtime.h>
#include <math.h>

// ---------------- problem constants ----------------
#define H1 128
#define W1 160
#define H2 256
#define W2 320
#define HWS1 (H1*W1)   // 20480
#define HWS2 (H2*W2)   // 81920
#define ND1 48
#define ND2 8
#define C1 32
#define C2 16

// ---------------- scratch (device globals; no allocation allowed) ----------------
__device__ float g_rot[2][2][9];
__device__ float g_trans[2][2][3];
__device__ float g_dmin, g_dstep;
__device__ float g_pad[32];

// 27 channel-reduced conv planes. stage1: 27*48*20480 floats (106MB). stage2 fits.
__device__ float g_G[27 * ND1 * HWS1];
__device__ float g_cost[ND1 * HWS1];       // stage2: 8*81920 fits
__device__ float g_bs[2 * HWS2];           // stage-2 per-pixel depth base/step
// channel-interleaved features: (3, C/4, HW, 4) -> float4 per (v,cg,pixel)
// max(3*8*20480, 3*4*81920) = 983040 float4
__device__ float4 g_ft[3 * (C2/4) * HWS2];

// ---------------- setup ----------------
__device__ void mat4_inv_d(const double* M, double* out) {
    double a[4][8];
    for (int i = 0; i < 4; i++)
        for (int j = 0; j < 4; j++) { a[i][j] = M[i*4+j]; a[i][j+4] = (i==j) ? 1.0 : 0.0; }
    for (int col = 0; col < 4; col++) {
        int piv = col; double best = fabs(a[col][col]);
        for (int r = col+1; r < 4; r++) if (fabs(a[r][col]) > best) { best = fabs(a[r][col]); piv = r; }
        if (piv != col) for (int j = 0; j < 8; j++) { double t = a[col][j]; a[col][j] = a[piv][j]; a[piv][j] = t; }
        double d = a[col][col];
        for (int j = 0; j < 8; j++) a[col][j] /= d;
        for (int r = 0; r < 4; r++) if (r != col) {
            double f = a[r][col];
            for (int j = 0; j < 8; j++) a[r][j] -= f * a[col][j];
        }
    }
    for (int i = 0; i < 4; i++) for (int j = 0; j < 4; j++) out[i*4+j] = a[i][j+4];
}

__global__ void setup_kernel(const float* __restrict__ proj1,
                             const float* __restrict__ proj2,
                             const float* __restrict__ depthv) {
    if (threadIdx.x != 0 || blockIdx.x != 0) return;
    for (int s = 0; s < 2; s++) {
        const float* P = s ? proj2 : proj1;   // (3 views, 2, 4, 4)
        double comp[3][16];
        for (int v = 0; v < 3; v++) {
            const float* E   = P + v*32;
            const float* Kin = P + v*32 + 16;
            for (int i = 0; i < 16; i++) comp[v][i] = (double)E[i];
            for (int i = 0; i < 3; i++)
                for (int j = 0; j < 4; j++) {
                    double t = 0.0;
                    for (int k = 0; k < 3; k++) t += (double)Kin[i*4+k] * (double)E[k*4+j];
                    comp[v][i*4+j] = t;
                }
        }
        double inv[16];
        mat4_inv_d(comp[0], inv);
        for (int v = 1; v < 3; v++) {
            double R[16];
            for (int i = 0; i < 4; i++)
                for (int j = 0; j < 4; j++) {
                    double t = 0.0;
                    for (int k = 0; k < 4; k++) t += comp[v][i*4+k] * inv[k*4+j];
                    R[i*4+j] = t;
                }
            for (int i = 0; i < 3; i++) {
                for (int j = 0; j < 3; j++) g_rot[s][v-1][i*3+j] = (float)R[i*4+j];
                g_trans[s][v-1][i] = (float)R[i*4+3];
            }
        }
    }
    g_dmin  = depthv[0];
    g_dstep = (depthv[ND1-1] - depthv[0]) / (float)(ND1 - 1);
}

__global__ void pad_kernel(int v) {
    if (blockIdx.x == 0 && threadIdx.x == 0) g_pad[v] = (float)v;
}

// ---------------- feature transpose: (3,C,H,W) -> (3,C/4,HW) of float4 ----------------
template<int C, int HW>
__global__ void __launch_bounds__(256)
transpose_kernel(const float* __restrict__ feats) {
    int i = blockIdx.x * blockDim.x + threadIdx.x;
    if (i >= 3 * (C/4) * HW) return;
    int hw = i % HW;
    int t  = i / HW;
    int cg = t % (C/4);
    int v  = t / (C/4);
    const float* src = feats + ((size_t)(v*C + cg*4)) * HW + hw;
    float4 val;
    val.x = src[0];
    val.y = src[HW];
    val.z = src[2*(size_t)HW];
    val.w = src[3*(size_t)HW];
    g_ft[i] = val;
}

// ---------------- 2x bilinear upsample sample ----------------
__device__ __forceinline__ float resize2x_sample(const float* __restrict__ src, int h, int w) {
    float fy = 0.5f * (float)h - 0.25f;
    float fx = 0.5f * (float)w - 0.25f;
    float y0f = floorf(fy), x0f = floorf(fx);
    float ty = fy - y0f, tx = fx - x0f;
    int y0 = (int)y0f, x0 = (int)x0f;
    int y0c = min(max(y0, 0), H1-1), y1c = min(max(y0+1, 0), H1-1);
    int x0c = min(max(x0, 0), W1-1), x1c = min(max(x0+1, 0), W1-1);
    float v00 = src[y0c*W1 + x0c], v01 = src[y0c*W1 + x1c];
    float v10 = src[y1c*W1 + x0c], v11 = src[y1c*W1 + x1c];
    return (v00*(1.f-tx) + v01*tx)*(1.f-ty) + (v10*(1.f-tx) + v11*tx)*ty;
}

__global__ void bs2_kernel(const float* __restrict__ d1, const float* __restrict__ v1) {
    int p = blockIdx.x * blockDim.x + threadIdx.x;
    if (p >= HWS2) return;
    int h = p / W2, w = p % W2;
    float cd = resize2x_sample(d1, h, w);
    float cv = resize2x_sample(v1, h, w);
    float low  = -fminf(cd, cv);
    g_bs[p]        = cd + low + 1e-12f;
    g_bs[HWS2 + p] = (cv - low) / (float)(ND2 - 1);
}

// ---------------- pass1: warp + variance + channel-reduced conv taps ----------------
template<int C, int D, int H, int W, bool STAGE2>
__global__ void __launch_bounds__(128)
pass1_kernel(const float* __restrict__ wconv,   // (C, 27)
             int stage) {
    constexpr int HW = H * W;
    constexpr int CG = C / 4;

    // transposed weights: sw[k*C + c] = wconv[c*27 + k], read as float4 over c
    __shared__ float sw[27 * C];
    for (int i = threadIdx.x; i < 27*C; i += blockDim.x) {
        int k = i / C, c = i % C;
        sw[i] = wconv[c*27 + k];
    }
    __syncthreads();
    const float4* swv = reinterpret_cast<const float4*>(sw);

    int idx = blockIdx.x * blockDim.x + threadIdx.x;
    if (idx >= D * HW) return;
    int hw = idx % HW;
    int d  = idx / HW;
    int h = hw / W, w = hw % W;

    float base, step;
    if (STAGE2) { base = g_bs[hw]; step = g_bs[HWS2 + hw]; }
    else        { base = g_dmin;   step = g_dstep; }
    float depth = fmaf(step, (float)d, base);

    int   off[2][4];
    float wt[2][4];
    #pragma unroll
    for (int v = 0; v < 2; v++) {
        const float* R = g_rot[stage][v];
        const float* T = g_trans[stage][v];
        float fx = (float)w, fy = (float)h;
        float px = (R[0]*fx + R[1]*fy + R[2]) * depth + T[0];
        float py = (R[3]*fx + R[4]*fy + R[5]) * depth + T[1];
        float pz = (R[6]*fx + R[7]*fy + R[8]) * depth + T[2];
        float iz = __fdividef(1.0f, pz);
        float gx = px * iz / (0.5f*(float)(W-1)) - 1.0f;
        float gy = py * iz / (0.5f*(float)(H-1)) - 1.0f;
        float ix = ((gx + 1.0f)*(float)W - 1.0f) * 0.5f;
        float iy = ((gy + 1.0f)*(float)H - 1.0f) * 0.5f;
        ix = fminf(fmaxf(ix, -8.0f), (float)(W+8));
        iy = fminf(fmaxf(iy, -8.0f), (float)(H+8));
        float x0f = floorf(ix), y0f = floorf(iy);
        float tx = ix - x0f, ty = iy - y0f;
        int x0 = (int)x0f, y0 = (int)y0f;
        bool vx0 = (x0   >= 0) && (x0   <= W-1);
        bool vx1 = (x0+1 >= 0) && (x0+1 <= W-1);
        bool vy0 = (y0   >= 0) && (y0   <= H-1);
        bool vy1 = (y0+1 >= 0) && (y0+1 <= H-1);
        int x0c = min(max(x0,   0), W-1), x1c = min(max(x0+1, 0), W-1);
        int y0c = min(max(y0,   0), H-1), y1c = min(max(y0+1, 0), H-1);
        off[v][0] = y0c*W + x0c;  off[v][1] = y0c*W + x1c;
        off[v][2] = y1c*W + x0c;  off[v][3] = y1c*W + x1c;
        wt[v][0] = (vx0 && vy0) ? (1.f-tx)*(1.f-ty) : 0.f;
        wt[v][1] = (vx1 && vy0) ? tx*(1.f-ty)       : 0.f;
        wt[v][2] = (vx0 && vy1) ? (1.f-tx)*ty       : 0.f;
        wt[v][3] = (vx1 && vy1) ? tx*ty             : 0.f;
    }

    const float4* ft0 = g_ft + hw;                     // ref, indexed by cg*HW
    const float4* ft1 = g_ft + (size_t)(1*CG) * HW;
    const float4* ft2 = g_ft + (size_t)(2*CG) * HW;

    float acc[27];
    #pragma unroll
    for (int k = 0; k < 27; k++) acc[k] = 0.f;

    #pragma unroll
    for (int cg = 0; cg < CG; cg++) {
        float4 r4 = ft0[(size_t)cg * HW];

        const float4* b1 = ft1 + (size_t)cg * HW;
        float4 p0 = b1[off[0][0]], p1 = b1[off[0][1]],
               p2 = b1[off[0][2]], p3 = b1[off[0][3]];
        float4 a1;
        a1.x = wt[0][0]*p0.x + wt[0][1]*p1.x + wt[0][2]*p2.x + wt[0][3]*p3.x;
        a1.y = wt[0][0]*p0.y + wt[0][1]*p1.y + wt[0][2]*p2.y + wt[0][3]*p3.y;
        a1.z = wt[0][0]*p0.z + wt[0][1]*p1.z + wt[0][2]*p2.z + wt[0][3]*p3.z;
        a1.w = wt[0][0]*p0.w + wt[0][1]*p1.w + wt[0][2]*p2.w + wt[0][3]*p3.w;

        const float4* b2 = ft2 + (size_t)cg * HW;
        float4 q0 = b2[off[1][0]], q1 = b2[off[1][1]],
               q2 = b2[off[1][2]], q3 = b2[off[1][3]];
        float4 a2;
        a2.x = wt[1][0]*q0.x + wt[1][1]*q1.x + wt[1][2]*q2.x + wt[1][3]*q3.x;
        a2.y = wt[1][0]*q0.y + wt[1][1]*q1.y + wt[1][2]*q2.y + wt[1][3]*q3.y;
        a2.z = wt[1][0]*q0.z + wt[1][1]*q1.z + wt[1][2]*q2.z + wt[1][3]*q3.z;
        a2.w = wt[1][0]*q0.w + wt[1][1]*q1.w + wt[1][2]*q2.w + wt[1][3]*q3.w;

        float4 var;
        {
            float s, q, m;
            s = r4.x + a1.x + a2.x; q = r4.x*r4.x + a1.x*a1.x + a2.x*a2.x;
            m = s*(1.f/3.f); var.x = q*(1.f/3.f) - m*m;
            s = r4.y + a1.y + a2.y; q = r4.y*r4.y + a1.y*a1.y + a2.y*a2.y;
            m = s*(1.f/3.f); var.y = q*(1.f/3.f) - m*m;
            s = r4.z + a1.z + a2.z; q = r4.z*r4.z + a1.z*a1.z + a2.z*a2.z;
            m = s*(1.f/3.f); var.z = q*(1.f/3.f) - m*m;
            s = r4.w + a1.w + a2.w; q = r4.w*r4.w + a1.w*a1.w + a2.w*a2.w;
            m = s*(1.f/3.f); var.w = q*(1.f/3.f) - m*m;
        }

        #pragma unroll
        for (int k = 0; k < 27; k++) {
            float4 wv = swv[k*CG + cg];
            acc[k] = fmaf(var.x, wv.x, acc[k]);
            acc[k] = fmaf(var.y, wv.y, acc[k]);
            acc[k] = fmaf(var.z, wv.z, acc[k]);
            acc[k] = fmaf(var.w, wv.w, acc[k]);
        }
    }

    #pragma unroll
    for (int k = 0; k < 27; k++)
        g_G[(size_t)k*(D*HW) + idx] = acc[k];
}

// ---------------- cost: 27-tap shifted-plane sum (zero-pad SAME) ----------------
template<int D, int H, int W>
__global__ void __launch_bounds__(256)
cost_kernel(const float* __restrict__ bias) {
    constexpr int HW = H * W;
    int idx = blockIdx.x * blockDim.x + threadIdx.x;
    if (idx >= D * HW) return;
    int hw = idx % HW;
    int d  = idx / HW;
    int h = hw / W, w = hw % W;
    float s = bias[0];
    #pragma unroll
    for (int kd = 0; kd < 3; kd++) {
        int dd = d + kd - 1;
        if (dd < 0 || dd >= D) continue;
        #pragma unroll
        for (int kh = 0; kh < 3; kh++) {
            int hh = h + kh - 1;
            if (hh < 0 || hh >= H) continue;
            #pragma unroll
            for (int kw = 0; kw < 3; kw++) {
                int ww = w + kw - 1;
                if (ww < 0 || ww >= W) continue;
                s += g_G[(size_t)(kd*9 + kh*3 + kw)*(D*HW) + (size_t)dd*HW + hh*W + ww];
            }
        }
    }
    g_cost[idx] = s;
}

// ---------------- per-pixel epilogue ----------------
template<int D, int H, int W, bool STAGE2>
__global__ void __launch_bounds__(256)
pixel_kernel(float* __restrict__ outd,
             float* __restrict__ outc,
             float* __restrict__ outv) {
    constexpr int HW = H * W;
    int p = blockIdx.x * blockDim.x + threadIdx.x;
    if (p >= HW) return;

    float e[D];
    float mx = -1e30f;
    #pragma unroll
    for (int d = 0; d < D; d++) { e[d] = g_cost[(size_t)d*HW + p]; mx = fmaxf(mx, e[d]); }
    float sum = 0.f;
    #pragma unroll
    for (int d = 0; d < D; d++) { e[d] = expf(e[d] - mx); sum += e[d]; }
    float inv = 1.0f / sum;
    float m1 = 0.f;
    #pragma unroll
    for (int d = 0; d < D; d++) {
        float pr = e[d] * inv;
        e[d] = pr;
        m1 += pr * (float)d;
    }

    float base, step;
    if (STAGE2) { base = g_bs[p]; step = g_bs[HWS2 + p]; }
    else        { base = g_dmin; step = g_dstep; }

    float depth = fmaf(step, m1, base);
    float var = 0.f;
    #pragma unroll
    for (int d = 0; d < D; d++) {
        float t = step * ((float)d - m1);
        var += e[d] * t * t;
    }
    int di = min(max((int)m1, 0), D-1);
    float conf = 0.f;
    #pragma unroll
    for (int d = 0; d < D; d++)
        if (d >= di-1 && d <= di+2) conf += e[d];

    outd[p] = depth;
    outc[p] = conf;
    outv[p] = 1.5f * sqrtf(fmaxf(var, 0.f));
}

// ---------------- launch ----------------
extern "C" void kernel_launch(void* const* d_in, const int* in_sizes, int n_in,
                              void* d_out, int out_size) {
    const float* feats1 = (const float*)d_in[0];
    const float* feats2 = (const float*)d_in[1];
    const float* proj1  = (const float*)d_in[2];
    const float* proj2  = (const float*)d_in[3];
    const float* depthv = (const float*)d_in[4];
    const float* w1     = (const float*)d_in[6];
    const float* b1     = (const float*)d_in[7];
    const float* w2     = (const float*)d_in[8];
    const float* b2     = (const float*)d_in[9];

    float* out = (float*)d_out;
    float* o_d1 = out;
    float* o_c1 = out + HWS1;
    float* o_v1 = out + 2*HWS1;
    float* o_d2 = out + 3*HWS1;
    float* o_c2 = out + 3*HWS1 + HWS2;
    float* o_v2 = out + 3*HWS1 + 2*HWS2;

    setup_kernel<<<1, 1>>>(proj1, proj2, depthv);                 // 1
    transpose_kernel<C1, HWS1><<<(3*(C1/4)*HWS1 + 255)/256, 256>>>(feats1);  // 2
    pad_kernel<<<1, 32>>>(0);                                      // 3

    // ---- stage 1 (C=32, D=48, 128x160) ----
    {
        int nvox = ND1 * HWS1;   // 983040
        pass1_kernel<C1, ND1, H1, W1, false>                       // 4 (profiled)
            <<<(nvox + 127)/128, 128>>>(w1, 0);
        cost_kernel<ND1, H1, W1>
            <<<(nvox + 255)/256, 256>>>(b1);
        pixel_kernel<ND1, H1, W1, false>
            <<<(HWS1 + 255)/256, 256>>>(o_d1, o_c1, o_v1);
    }

    // ---- stage 2 (C=16, D=8, 256x320) ----
    {
        int nvox = ND2 * HWS2;   // 655360
        transpose_kernel<C2, HWS2><<<(3*(C2/4)*HWS2 + 255)/256, 256>>>(feats2);
        bs2_kernel<<<(HWS2 + 255)/256, 256>>>(o_d1, o_v1);
        pass1_kernel<C2, ND2, H2, W2, true>
            <<<(nvox + 127)/128, 128>>>(w2, 1);
        cost_kernel<ND2, H2, W2>
            <<<(nvox + 255)/256, 256>>>(b2);
        pixel_kernel<ND2, H2, W2, true>
            <<<(HWS2 + 255)/256, 256>>>(o_d2, o_c2, o_v2);
    }
}

// round 8
// speedup vs baseline: 2.1350x; 1.0694x over previous
#include <cuda_runtime.h>
#include <math.h>

// ---------------- problem constants ----------------
#define H1 128
#define W1 160
#define H2 256
#define W2 320
#define HWS1 (H1*W1)   // 20480
#define HWS2 (H2*W2)   // 81920
#define ND1 48
#define ND2 8
#define C1 32
#define C2 16

// ---------------- scratch (device globals; no allocation allowed) ----------------
__device__ float g_rot[2][2][9];
__device__ float g_trans[2][2][3];
__device__ float g_dmin, g_dstep;
__device__ float g_pad[32];

// 27 channel-reduced conv planes. stage1: 27*48*20480 floats (106MB). stage2 fits.
__device__ float g_G[27 * ND1 * HWS1];
__device__ float g_cost[ND1 * HWS1];       // stage2: 8*81920 fits
__device__ float g_bs[2 * HWS2];           // stage-2 per-pixel depth base/step
// channel-interleaved features: (3, C/4, HW) of float4
__device__ float4 g_ft[3 * (C2/4) * HWS2];

// ---------------- setup ----------------
__device__ void mat4_inv_d(const double* M, double* out) {
    double a[4][8];
    for (int i = 0; i < 4; i++)
        for (int j = 0; j < 4; j++) { a[i][j] = M[i*4+j]; a[i][j+4] = (i==j) ? 1.0 : 0.0; }
    for (int col = 0; col < 4; col++) {
        int piv = col; double best = fabs(a[col][col]);
        for (int r = col+1; r < 4; r++) if (fabs(a[r][col]) > best) { best = fabs(a[r][col]); piv = r; }
        if (piv != col) for (int j = 0; j < 8; j++) { double t = a[col][j]; a[col][j] = a[piv][j]; a[piv][j] = t; }
        double d = a[col][col];
        for (int j = 0; j < 8; j++) a[col][j] /= d;
        for (int r = 0; r < 4; r++) if (r != col) {
            double f = a[r][col];
            for (int j = 0; j < 8; j++) a[r][j] -= f * a[col][j];
        }
    }
    for (int i = 0; i < 4; i++) for (int j = 0; j < 4; j++) out[i*4+j] = a[i][j+4];
}

__global__ void setup_kernel(const float* __restrict__ proj1,
                             const float* __restrict__ proj2,
                             const float* __restrict__ depthv) {
    if (threadIdx.x != 0 || blockIdx.x != 0) return;
    for (int s = 0; s < 2; s++) {
        const float* P = s ? proj2 : proj1;   // (3 views, 2, 4, 4)
        double comp[3][16];
        for (int v = 0; v < 3; v++) {
            const float* E   = P + v*32;
            const float* Kin = P + v*32 + 16;
            for (int i = 0; i < 16; i++) comp[v][i] = (double)E[i];
            for (int i = 0; i < 3; i++)
                for (int j = 0; j < 4; j++) {
                    double t = 0.0;
                    for (int k = 0; k < 3; k++) t += (double)Kin[i*4+k] * (double)E[k*4+j];
                    comp[v][i*4+j] = t;
                }
        }
        double inv[16];
        mat4_inv_d(comp[0], inv);
        for (int v = 1; v < 3; v++) {
            double R[16];
            for (int i = 0; i < 4; i++)
                for (int j = 0; j < 4; j++) {
                    double t = 0.0;
                    for (int k = 0; k < 4; k++) t += comp[v][i*4+k] * inv[k*4+j];
                    R[i*4+j] = t;
                }
            for (int i = 0; i < 3; i++) {
                for (int j = 0; j < 3; j++) g_rot[s][v-1][i*3+j] = (float)R[i*4+j];
                g_trans[s][v-1][i] = (float)R[i*4+3];
            }
        }
    }
    g_dmin  = depthv[0];
    g_dstep = (depthv[ND1-1] - depthv[0]) / (float)(ND1 - 1);
}

__global__ void pad_kernel(int v) {
    if (blockIdx.x == 0 && threadIdx.x == 0) g_pad[v] = (float)v;
}

// ---------------- feature transpose: (3,C,H,W) -> (3,C/4,HW) of float4 ----------------
template<int C, int HW>
__global__ void __launch_bounds__(256)
transpose_kernel(const float* __restrict__ feats) {
    int i = blockIdx.x * blockDim.x + threadIdx.x;
    if (i >= 3 * (C/4) * HW) return;
    int hw = i % HW;
    int t  = i / HW;
    int cg = t % (C/4);
    int v  = t / (C/4);
    const float* src = feats + ((size_t)(v*C + cg*4)) * HW + hw;
    float4 val;
    val.x = src[0];
    val.y = src[HW];
    val.z = src[2*(size_t)HW];
    val.w = src[3*(size_t)HW];
    g_ft[i] = val;
}

// ---------------- 2x bilinear upsample sample ----------------
__device__ __forceinline__ float resize2x_sample(const float* __restrict__ src, int h, int w) {
    float fy = 0.5f * (float)h - 0.25f;
    float fx = 0.5f * (float)w - 0.25f;
    float y0f = floorf(fy), x0f = floorf(fx);
    float ty = fy - y0f, tx = fx - x0f;
    int y0 = (int)y0f, x0 = (int)x0f;
    int y0c = min(max(y0, 0), H1-1), y1c = min(max(y0+1, 0), H1-1);
    int x0c = min(max(x0, 0), W1-1), x1c = min(max(x0+1, 0), W1-1);
    float v00 = src[y0c*W1 + x0c], v01 = src[y0c*W1 + x1c];
    float v10 = src[y1c*W1 + x0c], v11 = src[y1c*W1 + x1c];
    return (v00*(1.f-tx) + v01*tx)*(1.f-ty) + (v10*(1.f-tx) + v11*tx)*ty;
}

__global__ void bs2_kernel(const float* __restrict__ d1, const float* __restrict__ v1) {
    int p = blockIdx.x * blockDim.x + threadIdx.x;
    if (p >= HWS2) return;
    int h = p / W2, w = p % W2;
    float cd = resize2x_sample(d1, h, w);
    float cv = resize2x_sample(v1, h, w);
    float low  = -fminf(cd, cv);
    g_bs[p]        = cd + low + 1e-12f;
    g_bs[HWS2 + p] = (cv - low) / (float)(ND2 - 1);
}

// ---------------- projection helper ----------------
template<int H, int W>
__device__ __forceinline__ void project_offsets(
    const float* __restrict__ R, const float* __restrict__ T,
    float fx, float fy, float depth, int* off, float* wt) {
    float px = (R[0]*fx + R[1]*fy + R[2]) * depth + T[0];
    float py = (R[3]*fx + R[4]*fy + R[5]) * depth + T[1];
    float pz = (R[6]*fx + R[7]*fy + R[8]) * depth + T[2];
    float iz = __fdividef(1.0f, pz);
    float gx = px * iz / (0.5f*(float)(W-1)) - 1.0f;
    float gy = py * iz / (0.5f*(float)(H-1)) - 1.0f;
    float ix = ((gx + 1.0f)*(float)W - 1.0f) * 0.5f;
    float iy = ((gy + 1.0f)*(float)H - 1.0f) * 0.5f;
    ix = fminf(fmaxf(ix, -8.0f), (float)(W+8));
    iy = fminf(fmaxf(iy, -8.0f), (float)(H+8));
    float x0f = floorf(ix), y0f = floorf(iy);
    float tx = ix - x0f, ty = iy - y0f;
    int x0 = (int)x0f, y0 = (int)y0f;
    bool vx0 = (x0   >= 0) && (x0   <= W-1);
    bool vx1 = (x0+1 >= 0) && (x0+1 <= W-1);
    bool vy0 = (y0   >= 0) && (y0   <= H-1);
    bool vy1 = (y0+1 >= 0) && (y0+1 <= H-1);
    int x0c = min(max(x0,   0), W-1), x1c = min(max(x0+1, 0), W-1);
    int y0c = min(max(y0,   0), H-1), y1c = min(max(y0+1, 0), H-1);
    off[0] = y0c*W + x0c;  off[1] = y0c*W + x1c;
    off[2] = y1c*W + x0c;  off[3] = y1c*W + x1c;
    wt[0] = (vx0 && vy0) ? (1.f-tx)*(1.f-ty) : 0.f;
    wt[1] = (vx1 && vy0) ? tx*(1.f-ty)       : 0.f;
    wt[2] = (vx0 && vy1) ? (1.f-tx)*ty       : 0.f;
    wt[3] = (vx1 && vy1) ? tx*ty             : 0.f;
}

__device__ __forceinline__ float4 gather4(const float4* __restrict__ b,
                                          const int* off, const float* wt) {
    float4 p0 = b[off[0]], p1 = b[off[1]], p2 = b[off[2]], p3 = b[off[3]];
    float4 a;
    a.x = wt[0]*p0.x + wt[1]*p1.x + wt[2]*p2.x + wt[3]*p3.x;
    a.y = wt[0]*p0.y + wt[1]*p1.y + wt[2]*p2.y + wt[3]*p3.y;
    a.z = wt[0]*p0.z + wt[1]*p1.z + wt[2]*p2.z + wt[3]*p3.z;
    a.w = wt[0]*p0.w + wt[1]*p1.w + wt[2]*p2.w + wt[3]*p3.w;
    return a;
}

__device__ __forceinline__ float4 var3(float4 r, float4 a1, float4 a2) {
    float4 o;
    float s, q, m;
    s = r.x + a1.x + a2.x; q = r.x*r.x + a1.x*a1.x + a2.x*a2.x;
    m = s*(1.f/3.f); o.x = q*(1.f/3.f) - m*m;
    s = r.y + a1.y + a2.y; q = r.y*r.y + a1.y*a1.y + a2.y*a2.y;
    m = s*(1.f/3.f); o.y = q*(1.f/3.f) - m*m;
    s = r.z + a1.z + a2.z; q = r.z*r.z + a1.z*a1.z + a2.z*a2.z;
    m = s*(1.f/3.f); o.z = q*(1.f/3.f) - m*m;
    s = r.w + a1.w + a2.w; q = r.w*r.w + a1.w*a1.w + a2.w*a2.w;
    m = s*(1.f/3.f); o.w = q*(1.f/3.f) - m*m;
    return o;
}

// ---------------- pass1: depth-PAIR per thread ----------------
// Thread handles voxels (2dp, 2dp+1) at one pixel: weight LDS loads, ref-view
// loads and index math are shared across the pair.
template<int C, int D, int H, int W, bool STAGE2>
__global__ void __launch_bounds__(128)
pass1_kernel(const float* __restrict__ wconv,   // (C, 27)
             int stage) {
    constexpr int HW = H * W;
    constexpr int CG = C / 4;

    // transposed weights: sw[k*C + c] = wconv[c*27 + k], read as float4 over c
    __shared__ float sw[27 * C];
    for (int i = threadIdx.x; i < 27*C; i += blockDim.x) {
        int k = i / C, c = i % C;
        sw[i] = wconv[c*27 + k];
    }
    __syncthreads();
    const float4* swv = reinterpret_cast<const float4*>(sw);

    int idx = blockIdx.x * blockDim.x + threadIdx.x;
    if (idx >= (D/2) * HW) return;
    int hw = idx % HW;
    int dp = idx / HW;
    int d0 = 2*dp;
    int h = hw / W, w = hw % W;

    float base, step;
    if (STAGE2) { base = g_bs[hw]; step = g_bs[HWS2 + hw]; }
    else        { base = g_dmin;   step = g_dstep; }
    float dep0 = fmaf(step, (float)d0,     base);
    float dep1 = fmaf(step, (float)(d0+1), base);

    int   off[2][2][4];   // [depth][view][corner]
    float wt[2][2][4];
    float fx = (float)w, fy = (float)h;
    #pragma unroll
    for (int v = 0; v < 2; v++) {
        const float* R = g_rot[stage][v];
        const float* T = g_trans[stage][v];
        project_offsets<H, W>(R, T, fx, fy, dep0, off[0][v], wt[0][v]);
        project_offsets<H, W>(R, T, fx, fy, dep1, off[1][v], wt[1][v]);
    }

    const float4* ft0 = g_ft + hw;
    const float4* ft1 = g_ft + (size_t)(1*CG) * HW;
    const float4* ft2 = g_ft + (size_t)(2*CG) * HW;

    float acc0[27], acc1[27];
    #pragma unroll
    for (int k = 0; k < 27; k++) { acc0[k] = 0.f; acc1[k] = 0.f; }

    #pragma unroll
    for (int cg = 0; cg < CG; cg++) {
        float4 r4 = ft0[(size_t)cg * HW];               // shared across pair
        const float4* b1 = ft1 + (size_t)cg * HW;
        const float4* b2 = ft2 + (size_t)cg * HW;

        float4 va = var3(r4, gather4(b1, off[0][0], wt[0][0]),
                             gather4(b2, off[0][1], wt[0][1]));
        float4 vb = var3(r4, gather4(b1, off[1][0], wt[1][0]),
                             gather4(b2, off[1][1], wt[1][1]));

        #pragma unroll
        for (int k = 0; k < 27; k++) {
            float4 wv = swv[k*CG + cg];                 // one load, both depths
            acc0[k] = fmaf(va.x, wv.x, acc0[k]);
            acc0[k] = fmaf(va.y, wv.y, acc0[k]);
            acc0[k] = fmaf(va.z, wv.z, acc0[k]);
            acc0[k] = fmaf(va.w, wv.w, acc0[k]);
            acc1[k] = fmaf(vb.x, wv.x, acc1[k]);
            acc1[k] = fmaf(vb.y, wv.y, acc1[k]);
            acc1[k] = fmaf(vb.z, wv.z, acc1[k]);
            acc1[k] = fmaf(vb.w, wv.w, acc1[k]);
        }
    }

    #pragma unroll
    for (int k = 0; k < 27; k++) {
        g_G[(size_t)k*(D*HW) + (size_t)d0*HW + hw]     = acc0[k];
        g_G[(size_t)k*(D*HW) + (size_t)(d0+1)*HW + hw] = acc1[k];
    }
}

// ---------------- cost: 27-tap shifted-plane sum, 4 pixels per thread ----------------
template<int D, int H, int W>
__global__ void __launch_bounds__(256)
cost_kernel(const float* __restrict__ bias) {
    constexpr int HW = H * W;
    constexpr int W4 = W / 4;
    int t = blockIdx.x * blockDim.x + threadIdx.x;
    if (t >= D * H * W4) return;
    int wq = (t % W4) * 4;
    int r  = t / W4;
    int h = r % H;
    int d = r / H;

    float bb = bias[0];
    float4 s = make_float4(bb, bb, bb, bb);

    #pragma unroll
    for (int kd = 0; kd < 3; kd++) {
        int dd = d + kd - 1;
        if (dd < 0 || dd >= D) continue;
        #pragma unroll
        for (int kh = 0; kh < 3; kh++) {
            int hh = h + kh - 1;
            if (hh < 0 || hh >= H) continue;
            #pragma unroll
            for (int kw = 0; kw < 3; kw++) {
                const float* row = g_G + (size_t)(kd*9 + kh*3 + kw)*(D*HW)
                                       + (size_t)dd*HW + (size_t)hh*W;
                float4 v = *reinterpret_cast<const float4*>(row + wq);
                if (kw == 0) {          // shift -1: cols wq-1..wq+2
                    float left = (wq > 0) ? row[wq-1] : 0.f;
                    s.x += left; s.y += v.x; s.z += v.y; s.w += v.z;
                } else if (kw == 1) {   // shift 0
                    s.x += v.x; s.y += v.y; s.z += v.z; s.w += v.w;
                } else {                // shift +1: cols wq+1..wq+4
                    float right = (wq + 4 < W) ? row[wq+4] : 0.f;
                    s.x += v.y; s.y += v.z; s.z += v.w; s.w += right;
                }
            }
        }
    }
    *reinterpret_cast<float4*>(g_cost + (size_t)d*HW + (size_t)h*W + wq) = s;
}

// ---------------- per-pixel epilogue ----------------
template<int D, int H, int W, bool STAGE2>
__global__ void __launch_bounds__(256)
pixel_kernel(float* __restrict__ outd,
             float* __restrict__ outc,
             float* __restrict__ outv) {
    constexpr int HW = H * W;
    int p = blockIdx.x * blockDim.x + threadIdx.x;
    if (p >= HW) return;

    float e[D];
    float mx = -1e30f;
    #pragma unroll
    for (int d = 0; d < D; d++) { e[d] = g_cost[(size_t)d*HW + p]; mx = fmaxf(mx, e[d]); }
    float sum = 0.f;
    #pragma unroll
    for (int d = 0; d < D; d++) { e[d] = expf(e[d] - mx); sum += e[d]; }
    float inv = 1.0f / sum;
    float m1 = 0.f;
    #pragma unroll
    for (int d = 0; d < D; d++) {
        float pr = e[d] * inv;
        e[d] = pr;
        m1 += pr * (float)d;
    }

    float base, step;
    if (STAGE2) { base = g_bs[p]; step = g_bs[HWS2 + p]; }
    else        { base = g_dmin; step = g_dstep; }

    float depth = fmaf(step, m1, base);
    float var = 0.f;
    #pragma unroll
    for (int d = 0; d < D; d++) {
        float t = step * ((float)d - m1);
        var += e[d] * t * t;
    }
    int di = min(max((int)m1, 0), D-1);
    float conf = 0.f;
    #pragma unroll
    for (int d = 0; d < D; d++)
        if (d >= di-1 && d <= di+2) conf += e[d];

    outd[p] = depth;
    outc[p] = conf;
    outv[p] = 1.5f * sqrtf(fmaxf(var, 0.f));
}

// ---------------- launch ----------------
extern "C" void kernel_launch(void* const* d_in, const int* in_sizes, int n_in,
                              void* d_out, int out_size) {
    const float* feats1 = (const float*)d_in[0];
    const float* feats2 = (const float*)d_in[1];
    const float* proj1  = (const float*)d_in[2];
    const float* proj2  = (const float*)d_in[3];
    const float* depthv = (const float*)d_in[4];
    const float* w1     = (const float*)d_in[6];
    const float* b1     = (const float*)d_in[7];
    const float* w2     = (const float*)d_in[8];
    const float* b2     = (const float*)d_in[9];

    float* out = (float*)d_out;
    float* o_d1 = out;
    float* o_c1 = out + HWS1;
    float* o_v1 = out + 2*HWS1;
    float* o_d2 = out + 3*HWS1;
    float* o_c2 = out + 3*HWS1 + HWS2;
    float* o_v2 = out + 3*HWS1 + 2*HWS2;

    setup_kernel<<<1, 1>>>(proj1, proj2, depthv);                             // 1
    transpose_kernel<C1, HWS1><<<(3*(C1/4)*HWS1 + 255)/256, 256>>>(feats1);   // 2
    pad_kernel<<<1, 32>>>(0);                                                  // 3

    // ---- stage 1 (C=32, D=48, 128x160) ----
    {
        int nthr = (ND1/2) * HWS1;   // 491520
        pass1_kernel<C1, ND1, H1, W1, false>                                   // 4 (profiled)
            <<<(nthr + 127)/128, 128>>>(w1, 0);
        cost_kernel<ND1, H1, W1>
            <<<(ND1*H1*(W1/4) + 255)/256, 256>>>(b1);
        pixel_kernel<ND1, H1, W1, false>
            <<<(HWS1 + 255)/256, 256>>>(o_d1, o_c1, o_v1);
    }

    // ---- stage 2 (C=16, D=8, 256x320) ----
    {
        int nthr = (ND2/2) * HWS2;   // 327680
        transpose_kernel<C2, HWS2><<<(3*(C2/4)*HWS2 + 255)/256, 256>>>(feats2);
        bs2_kernel<<<(HWS2 + 255)/256, 256>>>(o_d1, o_v1);
        pass1_kernel<C2, ND2, H2, W2, true>
            <<<(nthr + 127)/128, 128>>>(w2, 1);
        cost_kernel<ND2, H2, W2>
            <<<(ND2*H2*(W2/4) + 255)/256, 256>>>(b2);
        pixel_kernel<ND2, H2, W2, true>
            <<<(HWS2 + 255)/256, 256>>>(o_d2, o_c2, o_v2);
    }
}